// round 2
// baseline (speedup 1.0000x reference)
#include <cuda_runtime.h>
#include <cuda_bf16.h>
#include <stdint.h>

#define DEVINL __device__ __forceinline__

// ---------------------------------------------------------------------------
// Dims: z[N,64] -> h1[N,128] -> h2[N,128] -> b[N,12(pad16)] ; tile M=128
// ---------------------------------------------------------------------------
static constexpr int TILE_M = 128;

// bf16 pitches (elements / bytes) chosen for conflict-free ldmatrix (+4 banks/row)
static constexpr int PZ  = 72;   static constexpr int PZB = 144;   // k=64 arrays
static constexpr int PH  = 136;  static constexpr int PHB = 272;   // k=128 arrays

// gmem weight image offsets (bytes) — same layout copied to smem
static constexpr unsigned OFF_W1H = 0;                    // [128][72] bf16
static constexpr unsigned OFF_W1L = 18432;
static constexpr unsigned OFF_W2H = 36864;                // [128][136]
static constexpr unsigned OFF_W2L = 71680;
static constexpr unsigned OFF_W3H = 106496;               // [16][136]
static constexpr unsigned OFF_W3L = 110848;
static constexpr unsigned WB      = 115200;

// smem layout (bytes)
static constexpr unsigned ZH  = 115200;                   // [128][72] bf16
static constexpr unsigned ZL  = 133632;
static constexpr unsigned HH  = 152064;                   // [128][136] bf16
static constexpr unsigned HL  = 186880;
static constexpr unsigned B1O = 221696;                   // 128 f32
static constexpr unsigned B2O = 222208;                   // 128 f32
static constexpr unsigned B3O = 222720;                   // 16 f32
static constexpr unsigned SMT = 222784;

__device__ __align__(16) unsigned char g_wb[WB];

// ---------------------------------------------------------------------------
// helpers
// ---------------------------------------------------------------------------
DEVINL uint32_t smem_u32(const void* p) {
    uint32_t a;
    asm("{ .reg .u64 t; cvta.to.shared.u64 t, %1; cvt.u32.u64 %0, t; }" : "=r"(a) : "l"(p));
    return a;
}

#define LDSM4(R, ADDR) \
    asm volatile("ldmatrix.sync.aligned.m8n8.x4.shared.b16 {%0,%1,%2,%3},[%4];" \
                 : "=r"((R)[0]), "=r"((R)[1]), "=r"((R)[2]), "=r"((R)[3]) : "r"(ADDR))

#define MMA(C, A, B0, B1) \
    asm volatile("mma.sync.aligned.m16n8k16.row.col.f32.bf16.bf16.f32 " \
                 "{%0,%1,%2,%3},{%4,%5,%6,%7},{%8,%9},{%0,%1,%2,%3};" \
                 : "+f"((C)[0]), "+f"((C)[1]), "+f"((C)[2]), "+f"((C)[3]) \
                 : "r"((A)[0]), "r"((A)[1]), "r"((A)[2]), "r"((A)[3]), "r"(B0), "r"(B1))

DEVINL uint32_t bits2(__nv_bfloat162 v) { return *reinterpret_cast<uint32_t*>(&v); }

DEVINL void split2(float a, float b, uint32_t& hi, uint32_t& lo) {
    __nv_bfloat162 h = __floats2bfloat162_rn(a, b);
    float ha = __low2float(h), hb = __high2float(h);
    __nv_bfloat162 l = __floats2bfloat162_rn(a - ha, b - hb);
    hi = bits2(h);
    lo = bits2(l);
}

// ---------------------------------------------------------------------------
// prep: weights -> [n][k] hi/lo bf16, padded pitch
// ---------------------------------------------------------------------------
__global__ void tastenet_prep(const float* __restrict__ W1,
                              const float* __restrict__ W2,
                              const float* __restrict__ W3) {
    int i = blockIdx.x * blockDim.x + threadIdx.x;
    __nv_bfloat16* w1h = (__nv_bfloat16*)(g_wb + OFF_W1H);
    __nv_bfloat16* w1l = (__nv_bfloat16*)(g_wb + OFF_W1L);
    __nv_bfloat16* w2h = (__nv_bfloat16*)(g_wb + OFF_W2H);
    __nv_bfloat16* w2l = (__nv_bfloat16*)(g_wb + OFF_W2L);
    __nv_bfloat16* w3h = (__nv_bfloat16*)(g_wb + OFF_W3H);
    __nv_bfloat16* w3l = (__nv_bfloat16*)(g_wb + OFF_W3L);

    if (i < 128 * 64) {                       // W1 (64,128): n,k
        int n = i >> 6, k = i & 63;
        float w = W1[k * 128 + n];
        __nv_bfloat16 h = __float2bfloat16(w);
        w1h[n * PZ + k] = h;
        w1l[n * PZ + k] = __float2bfloat16(w - __bfloat162float(h));
    }
    if (i < 128 * 128) {                      // W2 (128,128)
        int n = i >> 7, k = i & 127;
        float w = W2[k * 128 + n];
        __nv_bfloat16 h = __float2bfloat16(w);
        w2h[n * PH + k] = h;
        w2l[n * PH + k] = __float2bfloat16(w - __bfloat162float(h));
    }
    if (i < 16 * 128) {                       // W3 (128,12) pad n to 16
        int n = i >> 7, k = i & 127;
        float w = (n < 12) ? W3[k * 12 + n] : 0.f;
        __nv_bfloat16 h = __float2bfloat16(w);
        w3h[n * PH + k] = h;
        w3l[n * PH + k] = __float2bfloat16(w - __bfloat162float(h));
    }
}

// ---------------------------------------------------------------------------
// main persistent kernel: 256 threads, each warp owns 16 rows per tile
// ---------------------------------------------------------------------------
__global__ void __launch_bounds__(256, 1)
tastenet_main(const float* __restrict__ x, const float* __restrict__ z,
              const float* __restrict__ b1, const float* __restrict__ b2,
              const float* __restrict__ b3, float* __restrict__ out,
              int num_tiles) {
    extern __shared__ __align__(16) unsigned char smem[];
    const int tid = threadIdx.x;

    // ---- one-time: copy weight image + biases into smem ----
    {
        const float4* s = reinterpret_cast<const float4*>(g_wb);
        float4* d = reinterpret_cast<float4*>(smem);
        for (int i = tid; i < (int)(WB / 16); i += 256) d[i] = s[i];
        float* sb1 = (float*)(smem + B1O);
        float* sb2 = (float*)(smem + B2O);
        float* sb3 = (float*)(smem + B3O);
        if (tid < 128) { sb1[tid] = b1[tid]; sb2[tid] = b2[tid]; }
        if (tid < 16)  sb3[tid] = (tid < 12) ? b3[tid] : 0.f;
    }
    __syncthreads();

    const uint32_t sb = smem_u32(smem);
    const int w = tid >> 5, l = tid & 31;
    const int g = l >> 2, q = l & 3;
    const int m0 = w * 16;
    const int qq = l >> 3, rr = l & 7;

    // ldmatrix lane base addresses (constant across tiles)
    const int arow = ((qq & 1) << 3) + rr;           // A matrices: +8 rows for q1,q3
    const int akof = (qq >> 1) << 4;                 // +16B k for q2,q3
    const int brow = ((qq >> 1) << 3) + rr;          // B matrices: +8 n for q2,q3
    const int bkof = (qq & 1) << 4;                  // +16B k for q1,q3
    const uint32_t aZH = sb + ZH + (m0 + arow) * PZB + akof;
    const uint32_t aZL = sb + ZL + (m0 + arow) * PZB + akof;
    const uint32_t aHH = sb + HH + (m0 + arow) * PHB + akof;
    const uint32_t aHL = sb + HL + (m0 + arow) * PHB + akof;
    const uint32_t bW1H = sb + OFF_W1H + brow * PZB + bkof;
    const uint32_t bW1L = sb + OFF_W1L + brow * PZB + bkof;
    const uint32_t bW2H = sb + OFF_W2H + brow * PHB + bkof;
    const uint32_t bW2L = sb + OFF_W2L + brow * PHB + bkof;
    const uint32_t bW3H = sb + OFF_W3H + brow * PHB + bkof;
    const uint32_t bW3L = sb + OFF_W3L + brow * PHB + bkof;

    const float* sb1 = (const float*)(smem + B1O);
    const float* sb2 = (const float*)(smem + B2O);
    const float* sb3 = (const float*)(smem + B3O);

    // ---- z prefetch for first tile ----
    float4 zr[8];
    int t = blockIdx.x;
    {
        const float4* p = reinterpret_cast<const float4*>(z);
#pragma unroll
        for (int j = 0; j < 8; j++)
            zr[j] = p[(t * 128 + m0 + j * 2 + (l >> 4)) * 16 + (l & 15)];
    }

    for (; t < num_tiles; t += gridDim.x) {
        __syncwarp();
        // ---- stage z (hi/lo bf16) into warp-private smem rows ----
#pragma unroll
        for (int j = 0; j < 8; j++) {
            int rl = m0 + j * 2 + (l >> 4);
            int qc = l & 15;
            float4 v = zr[j];
            uint32_t h01, l01, h23, l23;
            split2(v.x, v.y, h01, l01);
            split2(v.z, v.w, h23, l23);
            *(uint2*)(smem + ZH + rl * PZB + qc * 8) = make_uint2(h01, h23);
            *(uint2*)(smem + ZL + rl * PZB + qc * 8) = make_uint2(l01, l23);
        }
        __syncwarp();

        // ---- prefetch next tile's z while we compute ----
        if (t + (int)gridDim.x < num_tiles) {
            const float4* p = reinterpret_cast<const float4*>(z);
            int tn = t + gridDim.x;
#pragma unroll
            for (int j = 0; j < 8; j++)
                zr[j] = p[(tn * 128 + m0 + j * 2 + (l >> 4)) * 16 + (l & 15)];
        }

        float acc[16][4];
#pragma unroll
        for (int n = 0; n < 16; n++)
#pragma unroll
            for (int c = 0; c < 4; c++) acc[n][c] = 0.f;

        // ---- layer 1: K=64 ----
#pragma unroll
        for (int kt = 0; kt < 4; kt++) {
            uint32_t ah[4], al[4];
            LDSM4(ah, aZH + kt * 32);
            LDSM4(al, aZL + kt * 32);
#pragma unroll
            for (int np = 0; np < 8; np++) {
                uint32_t bh[4], bl[4];
                LDSM4(bh, bW1H + np * 16 * PZB + kt * 32);
                MMA(acc[2 * np],     ah, bh[0], bh[1]);
                MMA(acc[2 * np + 1], ah, bh[2], bh[3]);
                MMA(acc[2 * np],     al, bh[0], bh[1]);
                MMA(acc[2 * np + 1], al, bh[2], bh[3]);
                LDSM4(bl, bW1L + np * 16 * PZB + kt * 32);
                MMA(acc[2 * np],     ah, bl[0], bl[1]);
                MMA(acc[2 * np + 1], ah, bl[2], bl[3]);
            }
        }

        // ---- h1 = relu(acc + b1) -> smem hi/lo ----
        __syncwarp();
#pragma unroll
        for (int n = 0; n < 16; n++) {
            int colb = n * 8 + 2 * q;
            float2 bb = *(const float2*)(smem + B1O + colb * 4);
            float v0 = fmaxf(acc[n][0] + bb.x, 0.f);
            float v1 = fmaxf(acc[n][1] + bb.y, 0.f);
            float v2 = fmaxf(acc[n][2] + bb.x, 0.f);
            float v3 = fmaxf(acc[n][3] + bb.y, 0.f);
            uint32_t h01, l01, h23, l23;
            split2(v0, v1, h01, l01);
            split2(v2, v3, h23, l23);
            *(uint32_t*)(smem + HH + (m0 + g) * PHB + colb * 2)     = h01;
            *(uint32_t*)(smem + HL + (m0 + g) * PHB + colb * 2)     = l01;
            *(uint32_t*)(smem + HH + (m0 + g + 8) * PHB + colb * 2) = h23;
            *(uint32_t*)(smem + HL + (m0 + g + 8) * PHB + colb * 2) = l23;
        }
        __syncwarp();

#pragma unroll
        for (int n = 0; n < 16; n++)
#pragma unroll
            for (int c = 0; c < 4; c++) acc[n][c] = 0.f;

        // ---- layer 2: K=128 ----
#pragma unroll
        for (int kt = 0; kt < 8; kt++) {
            uint32_t ah[4], al[4];
            LDSM4(ah, aHH + kt * 32);
            LDSM4(al, aHL + kt * 32);
#pragma unroll
            for (int np = 0; np < 8; np++) {
                uint32_t bh[4], bl[4];
                LDSM4(bh, bW2H + np * 16 * PHB + kt * 32);
                MMA(acc[2 * np],     ah, bh[0], bh[1]);
                MMA(acc[2 * np + 1], ah, bh[2], bh[3]);
                MMA(acc[2 * np],     al, bh[0], bh[1]);
                MMA(acc[2 * np + 1], al, bh[2], bh[3]);
                LDSM4(bl, bW2L + np * 16 * PHB + kt * 32);
                MMA(acc[2 * np],     ah, bl[0], bl[1]);
                MMA(acc[2 * np + 1], ah, bl[2], bl[3]);
            }
        }

        // ---- h2 = relu(acc + b2) -> smem hi/lo (overwrite h1) ----
        __syncwarp();
#pragma unroll
        for (int n = 0; n < 16; n++) {
            int colb = n * 8 + 2 * q;
            float2 bb = *(const float2*)(smem + B2O + colb * 4);
            float v0 = fmaxf(acc[n][0] + bb.x, 0.f);
            float v1 = fmaxf(acc[n][1] + bb.y, 0.f);
            float v2 = fmaxf(acc[n][2] + bb.x, 0.f);
            float v3 = fmaxf(acc[n][3] + bb.y, 0.f);
            uint32_t h01, l01, h23, l23;
            split2(v0, v1, h01, l01);
            split2(v2, v3, h23, l23);
            *(uint32_t*)(smem + HH + (m0 + g) * PHB + colb * 2)     = h01;
            *(uint32_t*)(smem + HL + (m0 + g) * PHB + colb * 2)     = l01;
            *(uint32_t*)(smem + HH + (m0 + g + 8) * PHB + colb * 2) = h23;
            *(uint32_t*)(smem + HL + (m0 + g + 8) * PHB + colb * 2) = l23;
        }
        __syncwarp();

        // ---- layer 3: [128] -> 16 (12 used) ----
        float a3[2][4];
#pragma unroll
        for (int n = 0; n < 2; n++)
#pragma unroll
            for (int c = 0; c < 4; c++) a3[n][c] = 0.f;
#pragma unroll
        for (int kt = 0; kt < 8; kt++) {
            uint32_t ah[4], al[4], bh[4], bl[4];
            LDSM4(ah, aHH + kt * 32);
            LDSM4(al, aHL + kt * 32);
            LDSM4(bh, bW3H + kt * 32);
            MMA(a3[0], ah, bh[0], bh[1]);
            MMA(a3[1], ah, bh[2], bh[3]);
            MMA(a3[0], al, bh[0], bh[1]);
            MMA(a3[1], al, bh[2], bh[3]);
            LDSM4(bl, bW3L + kt * 32);
            MMA(a3[0], ah, bl[0], bl[1]);
            MMA(a3[1], ah, bl[2], bl[3]);
        }

        // ---- epilogue: clamps, taste*x segment sums via quad shuffles ----
        {
            float b3A = sb3[2 * q], b3B = sb3[2 * q + 1];
            float b3C = sb3[8 + 2 * q], b3D = sb3[9 + 2 * q];
#pragma unroll
            for (int rs = 0; rs < 2; rs++) {
                float vA = a3[0][rs * 2 + 0] + b3A;   // col 2q
                float vB = a3[0][rs * 2 + 1] + b3B;   // col 2q+1
                float vC = a3[1][rs * 2 + 0] + b3C;   // col 8+2q
                float vD = a3[1][rs * 2 + 1] + b3D;   // col 9+2q
                if (q < 3)  vA = fminf(vA, 0.f);      // cols 0,2,4 clamp; col6 raw
                vB = fminf(vB, 0.f);                  // cols 1,3,5,7 clamp
                if (q == 0) vC = fminf(vC, 0.f);      // col 8 clamp

                int row = t * 128 + m0 + g + rs * 8;
                const float* xr = x + row * 9;
                float l0 = xr[q];        // x[q]
                float l1 = xr[4 + q];    // x[4+q]
                float l2 = xr[8];        // x[8] (same addr in quad)

                unsigned base = (unsigned)(l & ~3);
                float xAl = __shfl_sync(0xffffffffu, l0, base | ((2 * q) & 3));
                float xAh = __shfl_sync(0xffffffffu, l1, base | ((2 * q) & 3));
                float xBl = __shfl_sync(0xffffffffu, l0, base | ((2 * q + 1) & 3));
                float xBh = __shfl_sync(0xffffffffu, l1, base | ((2 * q + 1) & 3));
                float xA = (q < 2) ? xAl : xAh;
                float xB = (q < 2) ? xBl : xBh;

                float p0 = 0.f, p1 = 0.f, p2 = 0.f;
                if (q == 0) {
                    p0 = fmaf(xA, vA, xB * vB) + vD;  // x0*t0 + x1*t1 + i0
                    p2 = l2 * vC;                      // x8*t8
                } else if (q == 1) {
                    p0 = xA * vA;                      // x2*t2
                    p1 = xB * vB + vC;                 // x3*t3 + i1
                    p2 = vD;                           // i2
                } else if (q == 2) {
                    p1 = fmaf(xA, vA, xB * vB);        // x4*t4 + x5*t5
                } else {
                    p2 = fmaf(xA, vA, xB * vB);        // x6*t6 + x7*t7
                }
                p0 += __shfl_xor_sync(0xffffffffu, p0, 1);
                p0 += __shfl_xor_sync(0xffffffffu, p0, 2);
                p1 += __shfl_xor_sync(0xffffffffu, p1, 1);
                p1 += __shfl_xor_sync(0xffffffffu, p1, 2);
                p2 += __shfl_xor_sync(0xffffffffu, p2, 1);
                p2 += __shfl_xor_sync(0xffffffffu, p2, 2);
                if (q < 3) {
                    float val = (q == 0) ? p0 : (q == 1) ? p1 : p2;
                    out[row * 3 + q] = val;
                }
            }
        }
    }
}

// ---------------------------------------------------------------------------
// kernel_launch
// ---------------------------------------------------------------------------
extern "C" void kernel_launch(void* const* d_in, const int* in_sizes, int n_in,
                              void* d_out, int out_size) {
    const float* x  = (const float*)d_in[0];
    const float* z  = (const float*)d_in[1];
    const float* W1 = (const float*)d_in[2];
    const float* b1 = (const float*)d_in[3];
    const float* W2 = (const float*)d_in[4];
    const float* b2 = (const float*)d_in[5];
    const float* W3 = (const float*)d_in[6];
    const float* b3 = (const float*)d_in[7];
    float* out = (float*)d_out;

    const int n = in_sizes[1] / 64;
    const int num_tiles = n / TILE_M;

    tastenet_prep<<<64, 256>>>(W1, W2, W3);

    static int smem_set = 0;
    if (!smem_set) {
        cudaFuncSetAttribute(tastenet_main,
                             cudaFuncAttributeMaxDynamicSharedMemorySize, SMT);
        smem_set = 1;
    }
    int dev = 0, sms = 148;
    cudaGetDevice(&dev);
    cudaDeviceGetAttribute(&sms, cudaDevAttrMultiProcessorCount, dev);
    int grid = (sms < num_tiles) ? sms : num_tiles;
    if (grid < 1) grid = 1;

    tastenet_main<<<grid, 256, SMT>>>(x, z, b1, b2, b3, out, num_tiles);
}

// round 3
// speedup vs baseline: 1.1894x; 1.1894x over previous
#include <cuda_runtime.h>
#include <cuda_bf16.h>
#include <stdint.h>

#define DEVINL __device__ __forceinline__

// ---------------------------------------------------------------------------
// Dims: z[N,64] -> h1[N,128] -> h2[N,128] -> b[N,12(pad16)] ; tile M=128
// ---------------------------------------------------------------------------
static constexpr int TILE_M = 128;

// weight pitches (bf16 elems / bytes) for conflict-free ldmatrix
static constexpr int PZ  = 72;   static constexpr int PZB = 144;   // k=64
static constexpr int PH  = 136;  static constexpr int PHB = 272;   // k=128

// gmem weight image offsets (bytes) — same layout copied to smem
static constexpr unsigned OFF_W1H = 0;                    // [128][72] bf16
static constexpr unsigned OFF_W1L = 18432;
static constexpr unsigned OFF_W2H = 36864;                // [128][136]
static constexpr unsigned OFF_W2L = 71680;
static constexpr unsigned OFF_W3H = 106496;               // [16][136]
static constexpr unsigned OFF_W3L = 110848;
static constexpr unsigned WB      = 115200;

// raw z staging: 128 rows x 68 floats (272B pitch), double buffered
static constexpr unsigned ZPITCH = 272;                   // bytes per row
static constexpr unsigned ZRSZ   = 128 * ZPITCH;          // 34816
static constexpr unsigned ZR0    = WB;                    // 115200
static constexpr unsigned B1O    = ZR0 + 2 * ZRSZ;        // 184832
static constexpr unsigned B2O    = B1O + 512;
static constexpr unsigned B3O    = B2O + 512;
static constexpr unsigned SMT    = B3O + 64;              // 185920

__device__ __align__(16) unsigned char g_wb[WB];

// ---------------------------------------------------------------------------
// helpers
// ---------------------------------------------------------------------------
DEVINL uint32_t smem_u32(const void* p) {
    uint32_t a;
    asm("{ .reg .u64 t; cvta.to.shared.u64 t, %1; cvt.u32.u64 %0, t; }" : "=r"(a) : "l"(p));
    return a;
}

#define LDSM4(R, ADDR) \
    asm volatile("ldmatrix.sync.aligned.m8n8.x4.shared.b16 {%0,%1,%2,%3},[%4];" \
                 : "=r"((R)[0]), "=r"((R)[1]), "=r"((R)[2]), "=r"((R)[3]) : "r"(ADDR))

#define MMA(C, A, B0, B1) \
    asm volatile("mma.sync.aligned.m16n8k16.row.col.f32.bf16.bf16.f32 " \
                 "{%0,%1,%2,%3},{%4,%5,%6,%7},{%8,%9},{%0,%1,%2,%3};" \
                 : "+f"((C)[0]), "+f"((C)[1]), "+f"((C)[2]), "+f"((C)[3]) \
                 : "r"((A)[0]), "r"((A)[1]), "r"((A)[2]), "r"((A)[3]), "r"(B0), "r"(B1))

#define CP_ASYNC16(DST, SRC) \
    asm volatile("cp.async.cg.shared.global [%0], [%1], 16;" :: "r"(DST), "l"(SRC))
#define CP_COMMIT() asm volatile("cp.async.commit_group;")
#define CP_WAIT0()  asm volatile("cp.async.wait_group 0;" ::: "memory")

DEVINL uint32_t bits2(__nv_bfloat162 v) { return *reinterpret_cast<uint32_t*>(&v); }

DEVINL void split2(float a, float b, uint32_t& hi, uint32_t& lo) {
    __nv_bfloat162 h = __floats2bfloat162_rn(a, b);
    float ha = __low2float(h), hb = __high2float(h);
    __nv_bfloat162 l = __floats2bfloat162_rn(a - ha, b - hb);
    hi = bits2(h);
    lo = bits2(l);
}

// ---------------------------------------------------------------------------
// prep: weights -> [n][k] hi/lo bf16, padded pitch
// ---------------------------------------------------------------------------
__global__ void tastenet_prep(const float* __restrict__ W1,
                              const float* __restrict__ W2,
                              const float* __restrict__ W3) {
    int i = blockIdx.x * blockDim.x + threadIdx.x;
    __nv_bfloat16* w1h = (__nv_bfloat16*)(g_wb + OFF_W1H);
    __nv_bfloat16* w1l = (__nv_bfloat16*)(g_wb + OFF_W1L);
    __nv_bfloat16* w2h = (__nv_bfloat16*)(g_wb + OFF_W2H);
    __nv_bfloat16* w2l = (__nv_bfloat16*)(g_wb + OFF_W2L);
    __nv_bfloat16* w3h = (__nv_bfloat16*)(g_wb + OFF_W3H);
    __nv_bfloat16* w3l = (__nv_bfloat16*)(g_wb + OFF_W3L);

    if (i < 128 * 64) {                       // W1 (64,128): n,k
        int n = i >> 6, k = i & 63;
        float w = W1[k * 128 + n];
        __nv_bfloat16 h = __float2bfloat16(w);
        w1h[n * PZ + k] = h;
        w1l[n * PZ + k] = __float2bfloat16(w - __bfloat162float(h));
    }
    if (i < 128 * 128) {                      // W2 (128,128)
        int n = i >> 7, k = i & 127;
        float w = W2[k * 128 + n];
        __nv_bfloat16 h = __float2bfloat16(w);
        w2h[n * PH + k] = h;
        w2l[n * PH + k] = __float2bfloat16(w - __bfloat162float(h));
    }
    if (i < 16 * 128) {                       // W3 (128,12) pad n to 16
        int n = i >> 7, k = i & 127;
        float w = (n < 12) ? W3[k * 12 + n] : 0.f;
        __nv_bfloat16 h = __float2bfloat16(w);
        w3h[n * PH + k] = h;
        w3l[n * PH + k] = __float2bfloat16(w - __bfloat162float(h));
    }
}

// ---------------------------------------------------------------------------
// one K=16 step of a 3-term hi/lo GEMM: acc[16][4] += Ah*Bh + Al*Bh + Ah*Bl
// B frags loaded from smem; three passes give same-acc distance of 16 MMAs.
// ---------------------------------------------------------------------------
template <int PITCHB>
DEVINL void gemm_kt(float (*acc)[4], const uint32_t* ah, const uint32_t* al,
                    uint32_t bhAddr, uint32_t blAddr) {
    uint32_t bh[8][4];
#pragma unroll
    for (int np = 0; np < 8; np++) {
        LDSM4(bh[np], bhAddr + np * 16 * PITCHB);
        MMA(acc[2 * np],     ah, bh[np][0], bh[np][1]);
        MMA(acc[2 * np + 1], ah, bh[np][2], bh[np][3]);
    }
    uint32_t blc[4];
    LDSM4(blc, blAddr);
#pragma unroll
    for (int np = 0; np < 8; np++) {
        MMA(acc[2 * np],     al, bh[np][0], bh[np][1]);
        MMA(acc[2 * np + 1], al, bh[np][2], bh[np][3]);
    }
#pragma unroll
    for (int np = 0; np < 8; np++) {
        uint32_t bln[4];
        if (np < 7) LDSM4(bln, blAddr + (np + 1) * 16 * PITCHB);
        MMA(acc[2 * np],     ah, blc[0], blc[1]);
        MMA(acc[2 * np + 1], ah, blc[2], blc[3]);
        if (np < 7) {
#pragma unroll
            for (int r = 0; r < 4; r++) blc[r] = bln[r];
        }
    }
}

// relu(acc + bias) -> hi/lo bf16 A-fragments, fully in registers
DEVINL void transition(const float (*acc)[4], uint32_t (*AH)[4], uint32_t (*AL)[4],
                       const unsigned char* biasP, int q) {
#pragma unroll
    for (int j = 0; j < 8; j++) {
        float2 bA = *(const float2*)(biasP + (16 * j + 2 * q) * 4);
        float2 bB = *(const float2*)(biasP + (16 * j + 8 + 2 * q) * 4);
        float v00 = fmaxf(acc[2 * j][0] + bA.x, 0.f);
        float v01 = fmaxf(acc[2 * j][1] + bA.y, 0.f);
        float v02 = fmaxf(acc[2 * j][2] + bA.x, 0.f);
        float v03 = fmaxf(acc[2 * j][3] + bA.y, 0.f);
        float v10 = fmaxf(acc[2 * j + 1][0] + bB.x, 0.f);
        float v11 = fmaxf(acc[2 * j + 1][1] + bB.y, 0.f);
        float v12 = fmaxf(acc[2 * j + 1][2] + bB.x, 0.f);
        float v13 = fmaxf(acc[2 * j + 1][3] + bB.y, 0.f);
        split2(v00, v01, AH[j][0], AL[j][0]);
        split2(v02, v03, AH[j][1], AL[j][1]);
        split2(v10, v11, AH[j][2], AL[j][2]);
        split2(v12, v13, AH[j][3], AL[j][3]);
    }
}

// ---------------------------------------------------------------------------
// main persistent kernel: 256 threads, each warp owns 16 rows per tile
// ---------------------------------------------------------------------------
__global__ void __launch_bounds__(256, 1)
tastenet_main(const float* __restrict__ x, const float* __restrict__ z,
              const float* __restrict__ b1, const float* __restrict__ b2,
              const float* __restrict__ b3, float* __restrict__ out,
              int num_tiles) {
    extern __shared__ __align__(16) unsigned char smem[];
    const int tid = threadIdx.x;

    // ---- one-time: copy weight image + biases into smem ----
    {
        const float4* s = reinterpret_cast<const float4*>(g_wb);
        float4* d = reinterpret_cast<float4*>(smem);
        for (int i = tid; i < (int)(WB / 16); i += 256) d[i] = s[i];
        float* sb1 = (float*)(smem + B1O);
        float* sb2 = (float*)(smem + B2O);
        float* sb3 = (float*)(smem + B3O);
        if (tid < 128) { sb1[tid] = b1[tid]; sb2[tid] = b2[tid]; }
        if (tid < 16)  sb3[tid] = (tid < 12) ? b3[tid] : 0.f;
    }
    __syncthreads();

    const uint32_t sb = smem_u32(smem);
    const int w = tid >> 5, l = tid & 31;
    const int g = l >> 2, q = l & 3;
    const int m0 = w * 16;
    const int qq = l >> 3, rr = l & 7;

    // B-operand ldmatrix lane addresses (weights, constant across tiles)
    const int brow = ((qq >> 1) << 3) + rr;
    const int bkof = (qq & 1) << 4;
    const uint32_t bW1H = sb + OFF_W1H + brow * PZB + bkof;
    const uint32_t bW1L = sb + OFF_W1L + brow * PZB + bkof;
    const uint32_t bW2H = sb + OFF_W2H + brow * PHB + bkof;
    const uint32_t bW2L = sb + OFF_W2L + brow * PHB + bkof;
    const uint32_t bW3H = sb + OFF_W3H + brow * PHB + bkof;
    const uint32_t bW3L = sb + OFF_W3L + brow * PHB + bkof;

    const float* sb3 = (const float*)(smem + B3O);

    // cp.async lane mapping: 8 x 16B per thread covers this warp's 16 rows
    const int zrow = l >> 4;        // 0/1
    const int zcol = l & 15;        // 16B chunk in row

    int t = blockIdx.x;
    int pbuf = 0;
    // prologue prefetch: tile t -> buffer 0
    {
#pragma unroll
        for (int j = 0; j < 8; j++) {
            int row = m0 + j * 2 + zrow;
            uint32_t dst = sb + ZR0 + row * ZPITCH + zcol * 16;
            const float* src = z + ((size_t)t * 128 + row) * 64 + zcol * 4;
            CP_ASYNC16(dst, src);
        }
        CP_COMMIT();
    }

    for (; t < num_tiles; t += gridDim.x) {
        CP_WAIT0();
        __syncwarp();

        // ---- build layer-1 A fragments straight from raw fp32 z ----
        uint32_t A1H[4][4], A1L[4][4];
        {
            const unsigned char* r0p = smem + ZR0 + pbuf * ZRSZ + (m0 + g) * ZPITCH;
            const unsigned char* r8p = r0p + 8 * ZPITCH;
#pragma unroll
            for (int kt = 0; kt < 4; kt++) {
                float2 z00 = *(const float2*)(r0p + (16 * kt + 2 * q) * 4);
                float2 z10 = *(const float2*)(r8p + (16 * kt + 2 * q) * 4);
                float2 z01 = *(const float2*)(r0p + (16 * kt + 2 * q + 8) * 4);
                float2 z11 = *(const float2*)(r8p + (16 * kt + 2 * q + 8) * 4);
                split2(z00.x, z00.y, A1H[kt][0], A1L[kt][0]);
                split2(z10.x, z10.y, A1H[kt][1], A1L[kt][1]);
                split2(z01.x, z01.y, A1H[kt][2], A1L[kt][2]);
                split2(z11.x, z11.y, A1H[kt][3], A1L[kt][3]);
            }
        }

        // ---- prefetch next tile's z into the other buffer ----
        if (t + (int)gridDim.x < num_tiles) {
            int tn = t + gridDim.x;
            uint32_t zb = sb + ZR0 + (pbuf ^ 1) * ZRSZ;
#pragma unroll
            for (int j = 0; j < 8; j++) {
                int row = m0 + j * 2 + zrow;
                uint32_t dst = zb + row * ZPITCH + zcol * 16;
                const float* src = z + ((size_t)tn * 128 + row) * 64 + zcol * 4;
                CP_ASYNC16(dst, src);
            }
            CP_COMMIT();
        }

        // ---- prefetch x for the epilogue ----
        const int row0 = t * 128 + m0 + g;
        float xp[2][3];
#pragma unroll
        for (int rs = 0; rs < 2; rs++) {
            const float* xr = x + (size_t)(row0 + rs * 8) * 9;
            xp[rs][0] = xr[q];
            xp[rs][1] = xr[4 + q];
            xp[rs][2] = xr[8];
        }

        float acc[16][4];
#pragma unroll
        for (int n = 0; n < 16; n++)
#pragma unroll
            for (int c = 0; c < 4; c++) acc[n][c] = 0.f;

        // ---- layer 1: K=64 ----
#pragma unroll
        for (int kt = 0; kt < 4; kt++)
            gemm_kt<PZB>(acc, A1H[kt], A1L[kt], bW1H + kt * 32, bW1L + kt * 32);

        // ---- h1 = relu(acc+b1) -> A2 frags (registers only) ----
        uint32_t A2H[8][4], A2L[8][4];
        transition(acc, A2H, A2L, smem + B1O, q);

#pragma unroll
        for (int n = 0; n < 16; n++)
#pragma unroll
            for (int c = 0; c < 4; c++) acc[n][c] = 0.f;

        // ---- layer 2: K=128 ----
#pragma unroll
        for (int kt = 0; kt < 8; kt++)
            gemm_kt<PHB>(acc, A2H[kt], A2L[kt], bW2H + kt * 32, bW2L + kt * 32);

        // ---- h2 = relu(acc+b2) -> A frags (reuse A2 arrays) ----
        transition(acc, A2H, A2L, smem + B2O, q);

        // ---- layer 3: [128] -> 16 (12 used), 3 acc sets to break chains ----
        float a3a[2][4], a3b[2][4], a3c[2][4];
#pragma unroll
        for (int n = 0; n < 2; n++)
#pragma unroll
            for (int c = 0; c < 4; c++) { a3a[n][c] = 0.f; a3b[n][c] = 0.f; a3c[n][c] = 0.f; }
#pragma unroll
        for (int kt = 0; kt < 8; kt++) {
            uint32_t bh[4], bl[4];
            LDSM4(bh, bW3H + kt * 32);
            LDSM4(bl, bW3L + kt * 32);
            MMA(a3a[0], A2H[kt], bh[0], bh[1]);
            MMA(a3a[1], A2H[kt], bh[2], bh[3]);
            MMA(a3b[0], A2L[kt], bh[0], bh[1]);
            MMA(a3b[1], A2L[kt], bh[2], bh[3]);
            MMA(a3c[0], A2H[kt], bl[0], bl[1]);
            MMA(a3c[1], A2H[kt], bl[2], bl[3]);
        }
        float a3[2][4];
#pragma unroll
        for (int n = 0; n < 2; n++)
#pragma unroll
            for (int c = 0; c < 4; c++) a3[n][c] = a3a[n][c] + a3b[n][c] + a3c[n][c];

        // ---- epilogue: clamps, taste*x segment sums via quad shuffles ----
        {
            float b3A = sb3[2 * q], b3B = sb3[2 * q + 1];
            float b3C = sb3[8 + 2 * q], b3D = sb3[9 + 2 * q];
#pragma unroll
            for (int rs = 0; rs < 2; rs++) {
                float vA = a3[0][rs * 2 + 0] + b3A;   // col 2q
                float vB = a3[0][rs * 2 + 1] + b3B;   // col 2q+1
                float vC = a3[1][rs * 2 + 0] + b3C;   // col 8+2q
                float vD = a3[1][rs * 2 + 1] + b3D;   // col 9+2q
                if (q < 3)  vA = fminf(vA, 0.f);      // cols 0,2,4 clamp; col6 raw
                vB = fminf(vB, 0.f);                  // cols 1,3,5,7 clamp
                if (q == 0) vC = fminf(vC, 0.f);      // col 8 clamp

                int row = row0 + rs * 8;
                float l0 = xp[rs][0];
                float l1 = xp[rs][1];
                float l2 = xp[rs][2];

                unsigned base = (unsigned)(l & ~3);
                float xAl = __shfl_sync(0xffffffffu, l0, base | ((2 * q) & 3));
                float xAh = __shfl_sync(0xffffffffu, l1, base | ((2 * q) & 3));
                float xBl = __shfl_sync(0xffffffffu, l0, base | ((2 * q + 1) & 3));
                float xBh = __shfl_sync(0xffffffffu, l1, base | ((2 * q + 1) & 3));
                float xA = (q < 2) ? xAl : xAh;
                float xB = (q < 2) ? xBl : xBh;

                float p0 = 0.f, p1 = 0.f, p2 = 0.f;
                if (q == 0) {
                    p0 = fmaf(xA, vA, xB * vB) + vD;  // x0*t0 + x1*t1 + i0
                    p2 = l2 * vC;                      // x8*t8
                } else if (q == 1) {
                    p0 = xA * vA;                      // x2*t2
                    p1 = xB * vB + vC;                 // x3*t3 + i1
                    p2 = vD;                           // i2
                } else if (q == 2) {
                    p1 = fmaf(xA, vA, xB * vB);        // x4*t4 + x5*t5
                } else {
                    p2 = fmaf(xA, vA, xB * vB);        // x6*t6 + x7*t7
                }
                p0 += __shfl_xor_sync(0xffffffffu, p0, 1);
                p0 += __shfl_xor_sync(0xffffffffu, p0, 2);
                p1 += __shfl_xor_sync(0xffffffffu, p1, 1);
                p1 += __shfl_xor_sync(0xffffffffu, p1, 2);
                p2 += __shfl_xor_sync(0xffffffffu, p2, 1);
                p2 += __shfl_xor_sync(0xffffffffu, p2, 2);
                if (q < 3) {
                    float val = (q == 0) ? p0 : (q == 1) ? p1 : p2;
                    out[(size_t)row * 3 + q] = val;
                }
            }
        }
        pbuf ^= 1;
    }
}

// ---------------------------------------------------------------------------
// kernel_launch
// ---------------------------------------------------------------------------
extern "C" void kernel_launch(void* const* d_in, const int* in_sizes, int n_in,
                              void* d_out, int out_size) {
    const float* x  = (const float*)d_in[0];
    const float* z  = (const float*)d_in[1];
    const float* W1 = (const float*)d_in[2];
    const float* b1 = (const float*)d_in[3];
    const float* W2 = (const float*)d_in[4];
    const float* b2 = (const float*)d_in[5];
    const float* W3 = (const float*)d_in[6];
    const float* b3 = (const float*)d_in[7];
    float* out = (float*)d_out;

    const int n = in_sizes[1] / 64;
    const int num_tiles = n / TILE_M;

    tastenet_prep<<<64, 256>>>(W1, W2, W3);

    static int smem_set = 0;
    if (!smem_set) {
        cudaFuncSetAttribute(tastenet_main,
                             cudaFuncAttributeMaxDynamicSharedMemorySize, SMT);
        smem_set = 1;
    }
    int dev = 0, sms = 148;
    cudaGetDevice(&dev);
    cudaDeviceGetAttribute(&sms, cudaDevAttrMultiProcessorCount, dev);
    int grid = (sms < num_tiles) ? sms : num_tiles;
    if (grid < 1) grid = 1;

    tastenet_main<<<grid, 256, SMT>>>(x, z, b1, b2, b3, out, num_tiles);
}

// round 8
// speedup vs baseline: 1.6511x; 1.3881x over previous
#include <cuda_runtime.h>
#include <cuda_bf16.h>
#include <stdint.h>

#define DEVINL __device__ __forceinline__

// ---------------------------------------------------------------------------
// Dims: z[N,64] -> h1[N,128] -> h2[N,128] -> b[N,12(pad16)] ; tile M=128
// All GEMMs single-pass tf32 (m16n8k8). K-rows of W2/W3 permuted by
// tau = [0,2,4,6,1,3,5,7] per 8-group so accumulator layout == next A layout.
// ---------------------------------------------------------------------------
static constexpr int TILE_M = 128;

// fp32 weight pitches (floats / bytes); +4 floats so ldmatrix rows land on
// distinct 16B bank groups (pitch mod 128B == 16)
static constexpr int P1  = 68;   static constexpr int P1B = 272;   // W1 k=64
static constexpr int P2  = 132;  static constexpr int P2B = 528;   // W2/W3 k=128

// gmem weight image offsets (bytes) — same layout copied to smem
static constexpr unsigned OFF_W1 = 0;                      // [128][68] f32
static constexpr unsigned OFF_W2 = 34816;                  // [128][132] f32
static constexpr unsigned OFF_W3 = 102400;                 // [16][132] f32
static constexpr unsigned WB     = 110848;

// raw z staging: 128 rows x 68 floats (272B pitch), double buffered
static constexpr unsigned ZPITCH = 272;
static constexpr unsigned ZRSZ   = 128 * ZPITCH;           // 34816
static constexpr unsigned ZR0    = WB;                     // 110848
static constexpr unsigned B1O    = ZR0 + 2 * ZRSZ;         // 180480
static constexpr unsigned B2O    = B1O + 512;
static constexpr unsigned B3O    = B2O + 512;
static constexpr unsigned SMT    = B3O + 64;               // 181568

__device__ __align__(16) unsigned char g_wb[WB];

// ---------------------------------------------------------------------------
// helpers
// ---------------------------------------------------------------------------
DEVINL uint32_t smem_u32(const void* p) {
    uint32_t a;
    asm("{ .reg .u64 t; cvta.to.shared.u64 t, %1; cvt.u32.u64 %0, t; }" : "=r"(a) : "l"(p));
    return a;
}

#define LDSM4(R, ADDR) \
    asm volatile("ldmatrix.sync.aligned.m8n8.x4.shared.b16 {%0,%1,%2,%3},[%4];" \
                 : "=r"((R)[0]), "=r"((R)[1]), "=r"((R)[2]), "=r"((R)[3]) : "r"(ADDR))

// tf32 MMA: D[16x8] += A[16x8] * B[8x8]
#define MMAT(C, A0, A1, A2, A3, B0, B1) \
    asm volatile("mma.sync.aligned.m16n8k8.row.col.f32.tf32.tf32.f32 " \
                 "{%0,%1,%2,%3},{%4,%5,%6,%7},{%8,%9},{%0,%1,%2,%3};" \
                 : "+f"((C)[0]), "+f"((C)[1]), "+f"((C)[2]), "+f"((C)[3]) \
                 : "r"(A0), "r"(A1), "r"(A2), "r"(A3), "r"(B0), "r"(B1))

#define CP_ASYNC16(DST, SRC) \
    asm volatile("cp.async.cg.shared.global [%0], [%1], 16;" :: "r"(DST), "l"(SRC))
#define CP_COMMIT() asm volatile("cp.async.commit_group;")
#define CP_WAIT0()  asm volatile("cp.async.wait_group 0;" ::: "memory")

DEVINL uint32_t cvt_tf32(float f) {
    uint32_t u;
    asm("cvt.rna.tf32.f32 %0, %1;" : "=r"(u) : "f"(f));
    return u;
}

// ---------------------------------------------------------------------------
// prep: weights -> [n][k] tf32-rounded fp32, W2/W3 k-rows tau-permuted
// ---------------------------------------------------------------------------
__global__ void tastenet_prep(const float* __restrict__ W1,
                              const float* __restrict__ W2,
                              const float* __restrict__ W3) {
    int i = blockIdx.x * blockDim.x + threadIdx.x;
    float* w1 = (float*)(g_wb + OFF_W1);
    float* w2 = (float*)(g_wb + OFF_W2);
    float* w3 = (float*)(g_wb + OFF_W3);

    if (i < 128 * 64) {                       // W1 (64,128) -> [n][k], natural
        int n = i >> 6, k = i & 63;
        uint32_t u = cvt_tf32(W1[k * 128 + n]);
        w1[n * P1 + k] = __uint_as_float(u);
    }
    if (i < 128 * 128) {                      // W2 (128,128) -> [n][p], k=tau(p)
        int n = i >> 7, p = i & 127;
        int pg = p & 7;
        int kl = (pg < 4) ? (2 * pg) : (2 * (pg - 4) + 1);
        int k = (p & ~7) + kl;
        uint32_t u = cvt_tf32(W2[k * 128 + n]);
        w2[n * P2 + p] = __uint_as_float(u);
    }
    if (i < 16 * 128) {                       // W3 (128,12) pad n to 16
        int n = i >> 7, p = i & 127;
        int pg = p & 7;
        int kl = (pg < 4) ? (2 * pg) : (2 * (pg - 4) + 1);
        int k = (p & ~7) + kl;
        float w = (n < 12) ? W3[k * 12 + n] : 0.f;
        uint32_t u = cvt_tf32(w);
        w3[n * P2 + p] = __uint_as_float(u);
    }
}

// ---------------------------------------------------------------------------
// one 16-wide K-chunk (two k-tiles) of a tf32 GEMM over N=128:
// two half passes over np to keep same-acc distance = 8
// ---------------------------------------------------------------------------
DEVINL void gemm_kp(float (*acc)[4], const uint32_t* Ae, const uint32_t* Ao,
                    uint32_t bAddr, int npStrideB) {
#pragma unroll
    for (int half = 0; half < 2; half++) {
        uint32_t B[8][4];
#pragma unroll
        for (int j = 0; j < 8; j++)
            LDSM4(B[j], bAddr + (half * 8 + j) * npStrideB);
#pragma unroll
        for (int j = 0; j < 8; j++)
            MMAT(acc[half * 8 + j], Ae[0], Ae[1], Ae[2], Ae[3], B[j][0], B[j][1]);
#pragma unroll
        for (int j = 0; j < 8; j++)
            MMAT(acc[half * 8 + j], Ao[0], Ao[1], Ao[2], Ao[3], B[j][2], B[j][3]);
    }
}

// relu(acc + bias) -> tf32 A-fragments, registers only.
// a0=c0, a1=c2, a2=c1, a3=c3 (tau permutation absorbs the col mapping)
DEVINL void transition(const float (*acc)[4], uint32_t (*A)[4],
                       const unsigned char* biasP, int q) {
#pragma unroll
    for (int np = 0; np < 16; np++) {
        float2 bb = *(const float2*)(biasP + (8 * np + 2 * q) * 4);
        float v0 = fmaxf(acc[np][0] + bb.x, 0.f);
        float v1 = fmaxf(acc[np][1] + bb.y, 0.f);
        float v2 = fmaxf(acc[np][2] + bb.x, 0.f);
        float v3 = fmaxf(acc[np][3] + bb.y, 0.f);
        A[np][0] = cvt_tf32(v0);
        A[np][1] = cvt_tf32(v2);
        A[np][2] = cvt_tf32(v1);
        A[np][3] = cvt_tf32(v3);
    }
}

// ---------------------------------------------------------------------------
// main persistent kernel: 256 threads, each warp owns 16 rows per tile
// ---------------------------------------------------------------------------
__global__ void __launch_bounds__(256, 1)
tastenet_main(const float* __restrict__ x, const float* __restrict__ z,
              const float* __restrict__ b1, const float* __restrict__ b2,
              const float* __restrict__ b3, float* __restrict__ out,
              int num_tiles) {
    extern __shared__ __align__(16) unsigned char smem[];
    const int tid = threadIdx.x;

    // ---- one-time: copy weight image + biases into smem ----
    {
        const float4* s = reinterpret_cast<const float4*>(g_wb);
        float4* d = reinterpret_cast<float4*>(smem);
        for (int i = tid; i < (int)(WB / 16); i += 256) d[i] = s[i];
        float* sb1 = (float*)(smem + B1O);
        float* sb2 = (float*)(smem + B2O);
        float* sb3 = (float*)(smem + B3O);
        if (tid < 128) { sb1[tid] = b1[tid]; sb2[tid] = b2[tid]; }
        if (tid < 16)  sb3[tid] = (tid < 12) ? b3[tid] : 0.f;
    }
    __syncthreads();

    const uint32_t sb = smem_u32(smem);
    const int w = tid >> 5, l = tid & 31;
    const int g = l >> 2, q = l & 3;
    const int m0 = w * 16;

    // ldmatrix lane base for tf32-pair trick:
    // lane l -> row (l&7), float-col 4*(l>>3)
    const uint32_t bW1 = sb + OFF_W1 + (l & 7) * P1B + (l >> 3) * 16;
    const uint32_t bW2 = sb + OFF_W2 + (l & 7) * P2B + (l >> 3) * 16;
    const uint32_t bW3 = sb + OFF_W3 + (l & 7) * P2B + (l >> 3) * 16;

    const float* sb3 = (const float*)(smem + B3O);

    // cp.async lane mapping: 8 x 16B per thread covers this warp's 16 rows
    const int zrow = l >> 4;
    const int zcol = l & 15;

    int t = blockIdx.x;
    int pbuf = 0;
    {
#pragma unroll
        for (int j = 0; j < 8; j++) {
            int row = m0 + j * 2 + zrow;
            uint32_t dst = sb + ZR0 + row * ZPITCH + zcol * 16;
            const float* src = z + ((size_t)t * 128 + row) * 64 + zcol * 4;
            CP_ASYNC16(dst, src);
        }
        CP_COMMIT();
    }

    for (; t < num_tiles; t += gridDim.x) {
        CP_WAIT0();
        __syncwarp();

        // ---- build layer-1 A fragments straight from raw fp32 z ----
        uint32_t A1[8][4];
        {
            const unsigned char* r0p = smem + ZR0 + pbuf * ZRSZ +
                                       (m0 + g) * ZPITCH + q * 4;
            const unsigned char* r8p = r0p + 8 * ZPITCH;
#pragma unroll
            for (int kt = 0; kt < 8; kt++) {
                A1[kt][0] = cvt_tf32(*(const float*)(r0p + kt * 32));
                A1[kt][1] = cvt_tf32(*(const float*)(r8p + kt * 32));
                A1[kt][2] = cvt_tf32(*(const float*)(r0p + kt * 32 + 16));
                A1[kt][3] = cvt_tf32(*(const float*)(r8p + kt * 32 + 16));
            }
        }

        // ---- prefetch next tile's z into the other buffer ----
        if (t + (int)gridDim.x < num_tiles) {
            int tn = t + gridDim.x;
            uint32_t zb = sb + ZR0 + (pbuf ^ 1) * ZRSZ;
#pragma unroll
            for (int j = 0; j < 8; j++) {
                int row = m0 + j * 2 + zrow;
                uint32_t dst = zb + row * ZPITCH + zcol * 16;
                const float* src = z + ((size_t)tn * 128 + row) * 64 + zcol * 4;
                CP_ASYNC16(dst, src);
            }
            CP_COMMIT();
        }

        // ---- prefetch x for the epilogue ----
        const int row0 = t * 128 + m0 + g;
        float xp[2][3];
#pragma unroll
        for (int rs = 0; rs < 2; rs++) {
            const float* xr = x + (size_t)(row0 + rs * 8) * 9;
            xp[rs][0] = xr[q];
            xp[rs][1] = xr[4 + q];
            xp[rs][2] = xr[8];
        }

        float acc[16][4];
#pragma unroll
        for (int n = 0; n < 16; n++)
#pragma unroll
            for (int c = 0; c < 4; c++) acc[n][c] = 0.f;

        // ---- layer 1: K=64 (4 kp chunks of 16) ----
#pragma unroll
        for (int kp = 0; kp < 4; kp++)
            gemm_kp(acc, A1[2 * kp], A1[2 * kp + 1], bW1 + kp * 64, 8 * P1B);

        // ---- h1 = relu(acc+b1) -> A2 frags (registers only) ----
        uint32_t A2[16][4];
        transition(acc, A2, smem + B1O, q);

#pragma unroll
        for (int n = 0; n < 16; n++)
#pragma unroll
            for (int c = 0; c < 4; c++) acc[n][c] = 0.f;

        // ---- layer 2: K=128 (8 kp chunks) ----
#pragma unroll
        for (int kp = 0; kp < 8; kp++)
            gemm_kp(acc, A2[2 * kp], A2[2 * kp + 1], bW2 + kp * 64, 8 * P2B);

        // ---- h2 = relu(acc+b2) -> A frags (reuse A2) ----
        transition(acc, A2, smem + B2O, q);

        // ---- layer 3: [128] -> 16, even/odd acc sets for dep distance ----
        float a3e[2][4], a3o[2][4];
#pragma unroll
        for (int n = 0; n < 2; n++)
#pragma unroll
            for (int c = 0; c < 4; c++) { a3e[n][c] = 0.f; a3o[n][c] = 0.f; }
#pragma unroll
        for (int kp = 0; kp < 8; kp++) {
            uint32_t B0[4], B1r[4];
            LDSM4(B0,  bW3 + kp * 64);
            LDSM4(B1r, bW3 + 8 * P2B + kp * 64);
            MMAT(a3e[0], A2[2 * kp][0], A2[2 * kp][1], A2[2 * kp][2], A2[2 * kp][3],
                 B0[0], B0[1]);
            MMAT(a3e[1], A2[2 * kp][0], A2[2 * kp][1], A2[2 * kp][2], A2[2 * kp][3],
                 B1r[0], B1r[1]);
            MMAT(a3o[0], A2[2 * kp + 1][0], A2[2 * kp + 1][1], A2[2 * kp + 1][2],
                 A2[2 * kp + 1][3], B0[2], B0[3]);
            MMAT(a3o[1], A2[2 * kp + 1][0], A2[2 * kp + 1][1], A2[2 * kp + 1][2],
                 A2[2 * kp + 1][3], B1r[2], B1r[3]);
        }
        float a3[2][4];
#pragma unroll
        for (int n = 0; n < 2; n++)
#pragma unroll
            for (int c = 0; c < 4; c++) a3[n][c] = a3e[n][c] + a3o[n][c];

        // ---- epilogue: clamps, taste*x segment sums via quad shuffles ----
        {
            float b3A = sb3[2 * q], b3B = sb3[2 * q + 1];
            float b3C = sb3[8 + 2 * q], b3D = sb3[9 + 2 * q];
#pragma unroll
            for (int rs = 0; rs < 2; rs++) {
                float vA = a3[0][rs * 2 + 0] + b3A;   // col 2q
                float vB = a3[0][rs * 2 + 1] + b3B;   // col 2q+1
                float vC = a3[1][rs * 2 + 0] + b3C;   // col 8+2q
                float vD = a3[1][rs * 2 + 1] + b3D;   // col 9+2q
                if (q < 3)  vA = fminf(vA, 0.f);      // cols 0,2,4 clamp; col6 raw
                vB = fminf(vB, 0.f);                  // cols 1,3,5,7 clamp
                if (q == 0) vC = fminf(vC, 0.f);      // col 8 clamp

                int row = row0 + rs * 8;
                float l0 = xp[rs][0];
                float l1 = xp[rs][1];
                float l2 = xp[rs][2];

                unsigned base = (unsigned)(l & ~3);
                float xAl = __shfl_sync(0xffffffffu, l0, base | ((2 * q) & 3));
                float xAh = __shfl_sync(0xffffffffu, l1, base | ((2 * q) & 3));
                float xBl = __shfl_sync(0xffffffffu, l0, base | ((2 * q + 1) & 3));
                float xBh = __shfl_sync(0xffffffffu, l1, base | ((2 * q + 1) & 3));
                float xA = (q < 2) ? xAl : xAh;
                float xB = (q < 2) ? xBl : xBh;

                float p0 = 0.f, p1 = 0.f, p2 = 0.f;
                if (q == 0) {
                    p0 = fmaf(xA, vA, xB * vB) + vD;  // x0*t0 + x1*t1 + i0
                    p2 = l2 * vC;                      // x8*t8
                } else if (q == 1) {
                    p0 = xA * vA;                      // x2*t2
                    p1 = xB * vB + vC;                 // x3*t3 + i1
                    p2 = vD;                           // i2
                } else if (q == 2) {
                    p1 = fmaf(xA, vA, xB * vB);        // x4*t4 + x5*t5
                } else {
                    p2 = fmaf(xA, vA, xB * vB);        // x6*t6 + x7*t7
                }
                p0 += __shfl_xor_sync(0xffffffffu, p0, 1);
                p0 += __shfl_xor_sync(0xffffffffu, p0, 2);
                p1 += __shfl_xor_sync(0xffffffffu, p1, 1);
                p1 += __shfl_xor_sync(0xffffffffu, p1, 2);
                p2 += __shfl_xor_sync(0xffffffffu, p2, 1);
                p2 += __shfl_xor_sync(0xffffffffu, p2, 2);
                if (q < 3) {
                    float val = (q == 0) ? p0 : (q == 1) ? p1 : p2;
                    out[(size_t)row * 3 + q] = val;
                }
            }
        }
        pbuf ^= 1;
    }
}

// ---------------------------------------------------------------------------
// kernel_launch
// ---------------------------------------------------------------------------
extern "C" void kernel_launch(void* const* d_in, const int* in_sizes, int n_in,
                              void* d_out, int out_size) {
    const float* x  = (const float*)d_in[0];
    const float* z  = (const float*)d_in[1];
    const float* W1 = (const float*)d_in[2];
    const float* b1 = (const float*)d_in[3];
    const float* W2 = (const float*)d_in[4];
    const float* b2 = (const float*)d_in[5];
    const float* W3 = (const float*)d_in[6];
    const float* b3 = (const float*)d_in[7];
    float* out = (float*)d_out;

    const int n = in_sizes[1] / 64;
    const int num_tiles = n / TILE_M;

    tastenet_prep<<<64, 256>>>(W1, W2, W3);

    static int smem_set = 0;
    if (!smem_set) {
        cudaFuncSetAttribute(tastenet_main,
                             cudaFuncAttributeMaxDynamicSharedMemorySize, SMT);
        smem_set = 1;
    }
    int dev = 0, sms = 148;
    cudaGetDevice(&dev);
    cudaDeviceGetAttribute(&sms, cudaDevAttrMultiProcessorCount, dev);
    int grid = (sms < num_tiles) ? sms : num_tiles;
    if (grid < 1) grid = 1;

    tastenet_main<<<grid, 256, SMT>>>(x, z, b1, b2, b3, out, num_tiles);
}